// round 7
// baseline (speedup 1.0000x reference)
#include <cuda_runtime.h>
#include <cuda_bf16.h>

#define N_NODES 20000
#define N_EDGES 320000

// Scratch (static __device__ arrays — no allocation allowed). 16B-aligned for
// float4 traffic and red.global.add.v4.f32.
__device__ __align__(16) float g_xr1[N_NODES * 128];  // x @ W1_rel
__device__ __align__(16) float g_h1 [N_NODES * 128];  // conv1 output (pre-relu)
__device__ __align__(16) float g_xr2[N_NODES * 64];   // relu(h1) @ W2_rel
__device__ __align__(16) float g_h2 [N_NODES * 64];   // conv2 output
__device__ __align__(16) float g_h3 [N_NODES * 128];  // relu(h2@lin1+b)
__device__ __align__(16) float g_h4 [N_NODES * 64];   // relu(h3@lin2+b)

// Canonical int32 edge arrays + dtype-detection flag
__device__ int g_src[N_EDGES];
__device__ int g_dst[N_EDGES];
__device__ int g_flag[1];

// ---------------------------------------------------------------------------
// Edge-index preparation: the reference asks JAX for int64 edge_index, but with
// default x64-disabled JAX this silently becomes int32. Detect on-device and
// normalize into g_src/g_dst (int32).
//
// Detection: view buffer as int32[2E] (safe lower bound for both dtypes).
//   int64 layout: words at odd indices are high halves of src values
//                 (all < 20000, nonneg) -> all zero.
//   int32 layout: odd words are src[1],src[3],... -> some nonzero (w.h.p.).
// ---------------------------------------------------------------------------
__global__ void flag_reset_kernel() { g_flag[0] = 0; }

__global__ __launch_bounds__(256) void detect_kernel(const int* __restrict__ w)
{
    int i = blockIdx.x * blockDim.x + threadIdx.x;        // odd-word index
    long long idx = 2LL * i + 1;
    if (idx < 2LL * N_EDGES) {
        if (w[idx] != 0) atomicOr(&g_flag[0], 1);
    }
}

__global__ __launch_bounds__(256) void convert_kernel(const int* __restrict__ w)
{
    int e = blockIdx.x * blockDim.x + threadIdx.x;
    if (e >= N_EDGES) return;
    if (g_flag[0]) {
        // int32 layout: [src[0..E), dst[0..E)]
        g_src[e] = w[e];
        g_dst[e] = w[N_EDGES + e];
    } else {
        // int64 little-endian: low word of element i at int32 index 2i
        g_src[e] = w[2LL * e];
        g_dst[e] = w[2LL * (N_EDGES + e)];
    }
}

// ---------------------------------------------------------------------------
// Core 64x64 fp32 GEMM tile worker: acc = (reluA? relu(A):A)[rows,K] @ W tile.
// 16x16 threads, 4x4 microtile, K-tiles of 16. Shared by both GEMM kernels.
// ---------------------------------------------------------------------------
__device__ __forceinline__ void gemm_tile(
    const float* __restrict__ A, const float* __restrict__ W,
    int M, int K, int N, int reluA,
    int rowTile, int colTile, float acc[4][4],
    float (*As)[65], float (*Ws)[65])
{
    const int tid = threadIdx.x;
    const int ar = tid >> 2;            // 0..63  (row within A tile)
    const int ak = (tid & 3) << 2;      // 0,4,8,12 (k within tile)
    const int wk = tid >> 4;            // 0..15  (k within tile)
    const int wc = (tid & 15) << 2;     // 0..60  (col within tile)
    const int arow = rowTile * 64 + ar;
    const int wcol = colTile * 64 + wc;
    const int tx = tid & 15;
    const int ty = tid >> 4;

    for (int k0 = 0; k0 < K; k0 += 16) {
        float4 av = make_float4(0.f, 0.f, 0.f, 0.f);
        if (arow < M)
            av = *reinterpret_cast<const float4*>(A + (size_t)arow * K + k0 + ak);
        if (reluA) {
            av.x = fmaxf(av.x, 0.f); av.y = fmaxf(av.y, 0.f);
            av.z = fmaxf(av.z, 0.f); av.w = fmaxf(av.w, 0.f);
        }
        As[ak + 0][ar] = av.x;
        As[ak + 1][ar] = av.y;
        As[ak + 2][ar] = av.z;
        As[ak + 3][ar] = av.w;

        float4 wv = make_float4(0.f, 0.f, 0.f, 0.f);
        if (wcol < N)
            wv = *reinterpret_cast<const float4*>(W + (size_t)(k0 + wk) * N + wcol);
        Ws[wk][wc + 0] = wv.x;
        Ws[wk][wc + 1] = wv.y;
        Ws[wk][wc + 2] = wv.z;
        Ws[wk][wc + 3] = wv.w;

        __syncthreads();

        #pragma unroll
        for (int kk = 0; kk < 16; kk++) {
            float a[4], w[4];
            #pragma unroll
            for (int i = 0; i < 4; i++) a[i] = As[kk][ty * 4 + i];
            #pragma unroll
            for (int j = 0; j < 4; j++) w[j] = Ws[kk][tx * 4 + j];
            #pragma unroll
            for (int i = 0; i < 4; i++)
                #pragma unroll
                for (int j = 0; j < 4; j++)
                    acc[i][j] = fmaf(a[i], w[j], acc[i][j]);
        }
        __syncthreads();
    }
}

__device__ __forceinline__ void gemm_store(
    const float* __restrict__ bias, float* __restrict__ C,
    int M, int N, int reluC, int rowTile, int colTile, float acc[4][4])
{
    const int tid = threadIdx.x;
    const int tx = tid & 15;
    const int ty = tid >> 4;
    const int row0 = rowTile * 64 + ty * 4;
    const int col0 = colTile * 64 + tx * 4;

    float bv[4] = {0.f, 0.f, 0.f, 0.f};
    if (bias && col0 + 3 < N) {
        bv[0] = __ldg(bias + col0 + 0);
        bv[1] = __ldg(bias + col0 + 1);
        bv[2] = __ldg(bias + col0 + 2);
        bv[3] = __ldg(bias + col0 + 3);
    }

    #pragma unroll
    for (int i = 0; i < 4; i++) {
        int r = row0 + i;
        if (r >= M || col0 + 3 >= N) continue;
        float4 o;
        o.x = acc[i][0] + bv[0];
        o.y = acc[i][1] + bv[1];
        o.z = acc[i][2] + bv[2];
        o.w = acc[i][3] + bv[3];
        if (reluC) {
            o.x = fmaxf(o.x, 0.f); o.y = fmaxf(o.y, 0.f);
            o.z = fmaxf(o.z, 0.f); o.w = fmaxf(o.w, 0.f);
        }
        *reinterpret_cast<float4*>(C + (size_t)r * N + col0) = o;
    }
}

// Single-output GEMM: C = act(A@W + bias)
__global__ __launch_bounds__(256) void gemm_kernel(
    const float* __restrict__ A, const float* __restrict__ W,
    const float* __restrict__ bias, float* __restrict__ C,
    int M, int K, int N, int reluA, int reluC)
{
    __shared__ float As[16][65];
    __shared__ float Ws[16][65];
    float acc[4][4] = {};
    gemm_tile(A, W, M, K, N, reluA, blockIdx.y, blockIdx.x, acc, As, Ws);
    gemm_store(bias, C, M, N, reluC, blockIdx.y, blockIdx.x, acc);
}

// Dual-output GEMM for GraphConv: one pass over A produces both
//   C_rel  = A' @ W_rel            (no bias)
//   C_root = A' @ W_root + b       (bias)
// where A' = reluA? relu(A) : A. gridDim.x = 2*(N/64); lower half -> rel,
// upper half -> root. Halves A HBM traffic vs two separate launches.
__global__ __launch_bounds__(256) void gemm_dual_kernel(
    const float* __restrict__ A,
    const float* __restrict__ W_rel,  float* __restrict__ C_rel,
    const float* __restrict__ W_root, const float* __restrict__ b_root,
    float* __restrict__ C_root,
    int M, int K, int N, int reluA)
{
    __shared__ float As[16][65];
    __shared__ float Ws[16][65];
    float acc[4][4] = {};

    const int nt = N / 64;                 // col tiles per output
    const int isRoot = blockIdx.x >= nt;
    const int colTile = isRoot ? blockIdx.x - nt : blockIdx.x;
    const float* W = isRoot ? W_root : W_rel;
    float* C = isRoot ? C_root : C_rel;
    const float* bias = isRoot ? b_root : nullptr;

    gemm_tile(A, W, M, K, N, reluA, blockIdx.y, colTile, acc, As, Ws);
    gemm_store(bias, C, M, N, /*reluC=*/0, blockIdx.y, colTile, acc);
}

// ---------------------------------------------------------------------------
// Edge scatter-add: out[dst[e]] += feat[src[e]], DIM floats per edge.
// One warp handles EPW = 32/(DIM/4) edges; each lane does one float4 chunk
// via red.global.add.v4.f32 (vector atomic, sm_90+).
// ---------------------------------------------------------------------------
template <int DIM>
__global__ __launch_bounds__(256) void scatter_kernel(
    const float* __restrict__ feat,
    float* __restrict__ out,
    int n_edges)
{
    constexpr int CH  = DIM / 4;   // float4 chunks per edge
    constexpr int EPW = 32 / CH;   // edges per warp
    const int warp = (blockIdx.x * blockDim.x + threadIdx.x) >> 5;
    const int lane = threadIdx.x & 31;
    const int sub  = lane / CH;    // edge slot within warp
    const int cc   = lane % CH;    // chunk index

    const int e = warp * EPW + sub;
    if (e >= n_edges) return;

    const int s = g_src[e];
    const int d = g_dst[e];

    const float4 v = *reinterpret_cast<const float4*>(feat + (size_t)s * DIM + cc * 4);
    float* p = out + (size_t)d * DIM + cc * 4;
    asm volatile("red.global.add.v4.f32 [%0], {%1, %2, %3, %4};"
                 :: "l"(p), "f"(v.x), "f"(v.y), "f"(v.z), "f"(v.w)
                 : "memory");
}

// ---------------------------------------------------------------------------
// Head: out = log_softmax(h4 @ lin3_w + lin3_b), K=64, N_CLASS=10.
// One warp per row; 10 warp reductions via shfl, lane 0 does the log-softmax.
// ---------------------------------------------------------------------------
__global__ __launch_bounds__(256) void head_kernel(
    const float* __restrict__ h4,
    const float* __restrict__ W,    // [64, 10]
    const float* __restrict__ b,    // [10]
    float* __restrict__ out,        // [M, 10]
    int M)
{
    const int warp = (blockIdx.x * blockDim.x + threadIdx.x) >> 5;
    const int lane = threadIdx.x & 31;
    if (warp >= M) return;

    const float a0 = h4[(size_t)warp * 64 + lane];
    const float a1 = h4[(size_t)warp * 64 + 32 + lane];

    float acc[10];
    #pragma unroll
    for (int c = 0; c < 10; c++)
        acc[c] = fmaf(a0, __ldg(W + lane * 10 + c),
                      a1 * __ldg(W + (32 + lane) * 10 + c));

    #pragma unroll
    for (int off = 16; off > 0; off >>= 1)
        #pragma unroll
        for (int c = 0; c < 10; c++)
            acc[c] += __shfl_down_sync(0xffffffffu, acc[c], off);

    if (lane == 0) {
        float m = -1e30f;
        #pragma unroll
        for (int c = 0; c < 10; c++) {
            acc[c] += __ldg(b + c);
            m = fmaxf(m, acc[c]);
        }
        float s = 0.f;
        #pragma unroll
        for (int c = 0; c < 10; c++) s += expf(acc[c] - m);
        const float lse = m + logf(s);
        #pragma unroll
        for (int c = 0; c < 10; c++)
            out[(size_t)warp * 10 + c] = acc[c] - lse;
    }
}

// ---------------------------------------------------------------------------
extern "C" void kernel_launch(void* const* d_in, const int* in_sizes, int n_in,
                              void* d_out, int out_size)
{
    const float* x       = (const float*)d_in[0];
    const int*   ei_raw  = (const int*)  d_in[1];   // int32 view; dtype auto-detected
    const float* W1_rel  = (const float*)d_in[2];
    const float* W1_root = (const float*)d_in[3];
    const float* b1      = (const float*)d_in[4];
    const float* W2_rel  = (const float*)d_in[5];
    const float* W2_root = (const float*)d_in[6];
    const float* b2      = (const float*)d_in[7];
    const float* lin1_w  = (const float*)d_in[8];
    const float* lin1_b  = (const float*)d_in[9];
    const float* lin2_w  = (const float*)d_in[10];
    const float* lin2_b  = (const float*)d_in[11];
    const float* lin3_w  = (const float*)d_in[12];
    const float* lin3_b  = (const float*)d_in[13];
    float* out = (float*)d_out;

    float *xr1, *h1, *xr2, *h2, *h3, *h4;
    cudaGetSymbolAddress((void**)&xr1, g_xr1);
    cudaGetSymbolAddress((void**)&h1,  g_h1);
    cudaGetSymbolAddress((void**)&xr2, g_xr2);
    cudaGetSymbolAddress((void**)&h2,  g_h2);
    cudaGetSymbolAddress((void**)&h3,  g_h3);
    cudaGetSymbolAddress((void**)&h4,  g_h4);

    // ---- Edge-index normalization (dtype auto-detect) ----
    flag_reset_kernel<<<1, 1>>>();
    detect_kernel<<<(N_EDGES + 255) / 256, 256>>>(ei_raw);
    convert_kernel<<<(N_EDGES + 255) / 256, 256>>>(ei_raw);

    const int mb = (N_NODES + 63) / 64;

    // ---- GraphConv 1: xr1 = x@W1_rel ; h1 = x@W1_root + b1 (one A pass) ----
    gemm_dual_kernel<<<dim3(4, mb), 256>>>(x, W1_rel, xr1, W1_root, b1, h1,
                                           N_NODES, 256, 128, 0);
    {
        // 128-dim: 1 edge per warp -> 8 edges per 256-thread block
        int blocks = (N_EDGES + 7) / 8;
        scatter_kernel<128><<<blocks, 256>>>(xr1, h1, N_EDGES);
    }

    // ---- GraphConv 2 (relu fused into A-load, one A pass) ----
    gemm_dual_kernel<<<dim3(2, mb), 256>>>(h1, W2_rel, xr2, W2_root, b2, h2,
                                           N_NODES, 128, 64, 1);
    {
        // 64-dim: 2 edges per warp -> 16 edges per block
        int blocks = (N_EDGES + 15) / 16;
        scatter_kernel<64><<<blocks, 256>>>(xr2, h2, N_EDGES);
    }

    // ---- MLP head ----
    gemm_kernel<<<dim3(2, mb), 256>>>(h2, lin1_w, lin1_b, h3, N_NODES, 64, 128, 0, 1);
    gemm_kernel<<<dim3(1, mb), 256>>>(h3, lin2_w, lin2_b, h4, N_NODES, 128, 64, 0, 1);

    {
        int blocks = (N_NODES * 32 + 255) / 256;
        head_kernel<<<blocks, 256>>>(h4, lin3_w, lin3_b, out, N_NODES);
    }
}

// round 9
// speedup vs baseline: 1.0273x; 1.0273x over previous
#include <cuda_runtime.h>
#include <cuda_bf16.h>

#define N_NODES 20000
#define N_EDGES 320000

// Scratch (static __device__ arrays — no allocation allowed). 16B-aligned.
__device__ __align__(16) float g_xr1[N_NODES * 128];  // x @ W1_rel
__device__ __align__(16) float g_h1 [N_NODES * 128];  // conv1 output (pre-relu)
__device__ __align__(16) float g_xr2[N_NODES * 64];   // relu(h1) @ W2_rel
__device__ __align__(16) float g_h2 [N_NODES * 64];   // conv2 output
__device__ __align__(16) float g_h3 [N_NODES * 128];  // relu(h2@lin1+b)
__device__ __align__(16) float g_h4 [N_NODES * 64];   // relu(h3@lin2+b)

// Canonical int32 edge arrays + dtype-detection flag
__device__ int g_src[N_EDGES];
__device__ int g_dst[N_EDGES];
__device__ int g_flag[1];

// ---------------------------------------------------------------------------
// Edge-index preparation (int32 vs int64 JAX ambiguity) — unchanged, verified.
// ---------------------------------------------------------------------------
__global__ void flag_reset_kernel() { g_flag[0] = 0; }

__global__ __launch_bounds__(256) void detect_kernel(const int* __restrict__ w)
{
    int i = blockIdx.x * blockDim.x + threadIdx.x;        // odd-word index
    long long idx = 2LL * i + 1;
    if (idx < 2LL * N_EDGES) {
        if (w[idx] != 0) atomicOr(&g_flag[0], 1);
    }
}

__global__ __launch_bounds__(256) void convert_kernel(const int* __restrict__ w)
{
    int e = blockIdx.x * blockDim.x + threadIdx.x;
    if (e >= N_EDGES) return;
    if (g_flag[0]) {
        g_src[e] = w[e];
        g_dst[e] = w[N_EDGES + e];
    } else {
        g_src[e] = w[2LL * e];
        g_dst[e] = w[2LL * (N_EDGES + e)];
    }
}

// ---------------------------------------------------------------------------
// GEMM core v2: BM=128, BN=64, BK=16, 128 threads, 8x8 microtile.
// Inner loop: 4x LDS.128 (16 floats) per 64 FFMA -> 0.25 smem-loads/FMA,
// half of the old 4x4 tile. L1-bound kernel => ~2x faster.
// As stored k-major transposed: As[k][row]; Ws[k][col]. Row strides are
// 16B multiples so float4 smem accesses stay aligned.
// ---------------------------------------------------------------------------
#define BM 128
#define BN 64
#define BK 16
#define AS_LD 132   // 128 + 4 pad (132*4B = 16B multiple)
#define WS_LD 68    // 64 + 4 pad  (272B = 16B multiple)

__device__ __forceinline__ void gemm_tile8(
    const float* __restrict__ A, const float* __restrict__ W,
    int M, int K, int N, int reluA,
    int rowTile, int colTile, float acc[8][8],
    float (*As)[AS_LD], float (*Ws)[WS_LD])
{
    const int tid = threadIdx.x;        // 0..127
    const int tx = tid & 7;             // 0..7   (col group)
    const int ty = tid >> 3;            // 0..15  (row group)

    const int arow = rowTile * BM + tid;        // each thread loads one A row
    const int wk   = tid >> 3;                  // 0..15 (k row of W tile)
    const int wc   = (tid & 7) * 8;             // 0,8,..56
    const int wcol = colTile * BN + wc;

    for (int k0 = 0; k0 < K; k0 += BK) {
        // ---- load A tile: 128 rows x 16 k, one row per thread (4x float4)
        float4 a0 = make_float4(0.f,0.f,0.f,0.f), a1 = a0, a2 = a0, a3 = a0;
        if (arow < M) {
            const float* p = A + (size_t)arow * K + k0;
            a0 = *reinterpret_cast<const float4*>(p + 0);
            a1 = *reinterpret_cast<const float4*>(p + 4);
            a2 = *reinterpret_cast<const float4*>(p + 8);
            a3 = *reinterpret_cast<const float4*>(p + 12);
        }
        if (reluA) {
            a0.x=fmaxf(a0.x,0.f); a0.y=fmaxf(a0.y,0.f); a0.z=fmaxf(a0.z,0.f); a0.w=fmaxf(a0.w,0.f);
            a1.x=fmaxf(a1.x,0.f); a1.y=fmaxf(a1.y,0.f); a1.z=fmaxf(a1.z,0.f); a1.w=fmaxf(a1.w,0.f);
            a2.x=fmaxf(a2.x,0.f); a2.y=fmaxf(a2.y,0.f); a2.z=fmaxf(a2.z,0.f); a2.w=fmaxf(a2.w,0.f);
            a3.x=fmaxf(a3.x,0.f); a3.y=fmaxf(a3.y,0.f); a3.z=fmaxf(a3.z,0.f); a3.w=fmaxf(a3.w,0.f);
        }
        As[ 0][tid]=a0.x; As[ 1][tid]=a0.y; As[ 2][tid]=a0.z; As[ 3][tid]=a0.w;
        As[ 4][tid]=a1.x; As[ 5][tid]=a1.y; As[ 6][tid]=a1.z; As[ 7][tid]=a1.w;
        As[ 8][tid]=a2.x; As[ 9][tid]=a2.y; As[10][tid]=a2.z; As[11][tid]=a2.w;
        As[12][tid]=a3.x; As[13][tid]=a3.y; As[14][tid]=a3.z; As[15][tid]=a3.w;

        // ---- load W tile: 16 k x 64 cols, 8 floats per thread (2x float4)
        {
            const float* p = W + (size_t)(k0 + wk) * N + wcol;
            float4 w0 = *reinterpret_cast<const float4*>(p + 0);
            float4 w1 = *reinterpret_cast<const float4*>(p + 4);
            *reinterpret_cast<float4*>(&Ws[wk][wc + 0]) = w0;
            *reinterpret_cast<float4*>(&Ws[wk][wc + 4]) = w1;
        }

        __syncthreads();

        #pragma unroll
        for (int kk = 0; kk < BK; kk++) {
            float4 va0 = *reinterpret_cast<const float4*>(&As[kk][ty * 8 + 0]);
            float4 va1 = *reinterpret_cast<const float4*>(&As[kk][ty * 8 + 4]);
            float4 vw0 = *reinterpret_cast<const float4*>(&Ws[kk][tx * 8 + 0]);
            float4 vw1 = *reinterpret_cast<const float4*>(&Ws[kk][tx * 8 + 4]);
            float a[8] = {va0.x, va0.y, va0.z, va0.w, va1.x, va1.y, va1.z, va1.w};
            float w[8] = {vw0.x, vw0.y, vw0.z, vw0.w, vw1.x, vw1.y, vw1.z, vw1.w};
            #pragma unroll
            for (int i = 0; i < 8; i++)
                #pragma unroll
                for (int j = 0; j < 8; j++)
                    acc[i][j] = fmaf(a[i], w[j], acc[i][j]);
        }

        __syncthreads();
    }
}

__device__ __forceinline__ void gemm_store8(
    const float* __restrict__ bias, float* __restrict__ C,
    int M, int N, int reluC, int rowTile, int colTile, float acc[8][8])
{
    const int tid = threadIdx.x;
    const int tx = tid & 7;
    const int ty = tid >> 3;
    const int row0 = rowTile * BM + ty * 8;
    const int col0 = colTile * BN + tx * 8;

    float bv[8];
    #pragma unroll
    for (int j = 0; j < 8; j++) bv[j] = bias ? __ldg(bias + col0 + j) : 0.f;

    #pragma unroll
    for (int i = 0; i < 8; i++) {
        int r = row0 + i;
        if (r >= M) break;
        float o[8];
        #pragma unroll
        for (int j = 0; j < 8; j++) {
            o[j] = acc[i][j] + bv[j];
            if (reluC) o[j] = fmaxf(o[j], 0.f);
        }
        float* p = C + (size_t)r * N + col0;
        *reinterpret_cast<float4*>(p + 0) = make_float4(o[0], o[1], o[2], o[3]);
        *reinterpret_cast<float4*>(p + 4) = make_float4(o[4], o[5], o[6], o[7]);
    }
}

// Single-output GEMM: C = act(A@W + bias)
__global__ __launch_bounds__(128) void gemm_kernel(
    const float* __restrict__ A, const float* __restrict__ W,
    const float* __restrict__ bias, float* __restrict__ C,
    int M, int K, int N, int reluA, int reluC)
{
    __shared__ float As[BK][AS_LD];
    __shared__ float Ws[BK][WS_LD];
    float acc[8][8] = {};
    gemm_tile8(A, W, M, K, N, reluA, blockIdx.y, blockIdx.x, acc, As, Ws);
    gemm_store8(bias, C, M, N, reluC, blockIdx.y, blockIdx.x, acc);
}

// Dual-output GEMM for GraphConv: one A pass -> C_rel (no bias) + C_root (+b).
// gridDim.x = 2*(N/64): lower half rel, upper half root.
__global__ __launch_bounds__(128) void gemm_dual_kernel(
    const float* __restrict__ A,
    const float* __restrict__ W_rel,  float* __restrict__ C_rel,
    const float* __restrict__ W_root, const float* __restrict__ b_root,
    float* __restrict__ C_root,
    int M, int K, int N, int reluA)
{
    __shared__ float As[BK][AS_LD];
    __shared__ float Ws[BK][WS_LD];
    float acc[8][8] = {};

    const int nt = N / BN;
    const int isRoot = blockIdx.x >= nt;
    const int colTile = isRoot ? blockIdx.x - nt : blockIdx.x;
    const float* W = isRoot ? W_root : W_rel;
    float* C = isRoot ? C_root : C_rel;
    const float* bias = isRoot ? b_root : nullptr;

    gemm_tile8(A, W, M, K, N, reluA, blockIdx.y, colTile, acc, As, Ws);
    gemm_store8(bias, C, M, N, /*reluC=*/0, blockIdx.y, colTile, acc);
}

// ---------------------------------------------------------------------------
// Edge scatter-add: out[dst[e]] += feat[src[e]], DIM floats per edge.
// red.global.add.v4.f32 vector atomics — unchanged, verified.
// ---------------------------------------------------------------------------
template <int DIM>
__global__ __launch_bounds__(256) void scatter_kernel(
    const float* __restrict__ feat,
    float* __restrict__ out,
    int n_edges)
{
    constexpr int CH  = DIM / 4;
    constexpr int EPW = 32 / CH;
    const int warp = (blockIdx.x * blockDim.x + threadIdx.x) >> 5;
    const int lane = threadIdx.x & 31;
    const int sub  = lane / CH;
    const int cc   = lane % CH;

    const int e = warp * EPW + sub;
    if (e >= n_edges) return;

    const int s = g_src[e];
    const int d = g_dst[e];

    const float4 v = *reinterpret_cast<const float4*>(feat + (size_t)s * DIM + cc * 4);
    float* p = out + (size_t)d * DIM + cc * 4;
    asm volatile("red.global.add.v4.f32 [%0], {%1, %2, %3, %4};"
                 :: "l"(p), "f"(v.x), "f"(v.y), "f"(v.z), "f"(v.w)
                 : "memory");
}

// ---------------------------------------------------------------------------
// Head: out = log_softmax(h4 @ lin3_w + lin3_b), K=64, N_CLASS=10 — unchanged.
// ---------------------------------------------------------------------------
__global__ __launch_bounds__(256) void head_kernel(
    const float* __restrict__ h4,
    const float* __restrict__ W,    // [64, 10]
    const float* __restrict__ b,    // [10]
    float* __restrict__ out,        // [M, 10]
    int M)
{
    const int warp = (blockIdx.x * blockDim.x + threadIdx.x) >> 5;
    const int lane = threadIdx.x & 31;
    if (warp >= M) return;

    const float a0 = h4[(size_t)warp * 64 + lane];
    const float a1 = h4[(size_t)warp * 64 + 32 + lane];

    float acc[10];
    #pragma unroll
    for (int c = 0; c < 10; c++)
        acc[c] = fmaf(a0, __ldg(W + lane * 10 + c),
                      a1 * __ldg(W + (32 + lane) * 10 + c));

    #pragma unroll
    for (int off = 16; off > 0; off >>= 1)
        #pragma unroll
        for (int c = 0; c < 10; c++)
            acc[c] += __shfl_down_sync(0xffffffffu, acc[c], off);

    if (lane == 0) {
        float m = -1e30f;
        #pragma unroll
        for (int c = 0; c < 10; c++) {
            acc[c] += __ldg(b + c);
            m = fmaxf(m, acc[c]);
        }
        float s = 0.f;
        #pragma unroll
        for (int c = 0; c < 10; c++) s += expf(acc[c] - m);
        const float lse = m + logf(s);
        #pragma unroll
        for (int c = 0; c < 10; c++)
            out[(size_t)warp * 10 + c] = acc[c] - lse;
    }
}

// ---------------------------------------------------------------------------
extern "C" void kernel_launch(void* const* d_in, const int* in_sizes, int n_in,
                              void* d_out, int out_size)
{
    const float* x       = (const float*)d_in[0];
    const int*   ei_raw  = (const int*)  d_in[1];
    const float* W1_rel  = (const float*)d_in[2];
    const float* W1_root = (const float*)d_in[3];
    const float* b1      = (const float*)d_in[4];
    const float* W2_rel  = (const float*)d_in[5];
    const float* W2_root = (const float*)d_in[6];
    const float* b2      = (const float*)d_in[7];
    const float* lin1_w  = (const float*)d_in[8];
    const float* lin1_b  = (const float*)d_in[9];
    const float* lin2_w  = (const float*)d_in[10];
    const float* lin2_b  = (const float*)d_in[11];
    const float* lin3_w  = (const float*)d_in[12];
    const float* lin3_b  = (const float*)d_in[13];
    float* out = (float*)d_out;

    float *xr1, *h1, *xr2, *h2, *h3, *h4;
    cudaGetSymbolAddress((void**)&xr1, g_xr1);
    cudaGetSymbolAddress((void**)&h1,  g_h1);
    cudaGetSymbolAddress((void**)&xr2, g_xr2);
    cudaGetSymbolAddress((void**)&h2,  g_h2);
    cudaGetSymbolAddress((void**)&h3,  g_h3);
    cudaGetSymbolAddress((void**)&h4,  g_h4);

    // ---- Edge-index normalization (dtype auto-detect) ----
    flag_reset_kernel<<<1, 1>>>();
    detect_kernel<<<(N_EDGES + 255) / 256, 256>>>(ei_raw);
    convert_kernel<<<(N_EDGES + 255) / 256, 256>>>(ei_raw);

    const int mbr = (N_NODES + BM - 1) / BM;   // 157

    // ---- GraphConv 1: xr1 = x@W1_rel ; h1 = x@W1_root + b1 (one A pass) ----
    gemm_dual_kernel<<<dim3(4, mbr), 128>>>(x, W1_rel, xr1, W1_root, b1, h1,
                                            N_NODES, 256, 128, 0);
    {
        int blocks = (N_EDGES + 7) / 8;
        scatter_kernel<128><<<blocks, 256>>>(xr1, h1, N_EDGES);
    }

    // ---- GraphConv 2 (relu fused into A-load, one A pass) ----
    gemm_dual_kernel<<<dim3(2, mbr), 128>>>(h1, W2_rel, xr2, W2_root, b2, h2,
                                            N_NODES, 128, 64, 1);
    {
        int blocks = (N_EDGES + 15) / 16;
        scatter_kernel<64><<<blocks, 256>>>(xr2, h2, N_EDGES);
    }

    // ---- MLP head ----
    gemm_kernel<<<dim3(2, mbr), 128>>>(h2, lin1_w, lin1_b, h3, N_NODES, 64, 128, 0, 1);
    gemm_kernel<<<dim3(1, mbr), 128>>>(h3, lin2_w, lin2_b, h4, N_NODES, 128, 64, 0, 1);

    {
        int blocks = (N_NODES * 32 + 255) / 256;
        head_kernel<<<blocks, 256>>>(h4, lin3_w, lin3_b, out, N_NODES);
    }
}

// round 10
// speedup vs baseline: 1.0977x; 1.0686x over previous
#include <cuda_runtime.h>
#include <cuda_bf16.h>
#include <cstdint>

#define N_NODES 20000
#define N_EDGES 320000

// Scratch (static __device__ arrays — no allocation allowed). 16B-aligned.
__device__ __align__(16) float g_xr1[N_NODES * 128];  // x @ W1_rel
__device__ __align__(16) float g_h1 [N_NODES * 128];  // conv1 output (pre-relu)
__device__ __align__(16) float g_xr2[N_NODES * 64];   // relu(h1) @ W2_rel
__device__ __align__(16) float g_h2 [N_NODES * 64];   // conv2 output
__device__ __align__(16) float g_h3 [N_NODES * 128];  // relu(h2@lin1+b)
__device__ __align__(16) float g_h4 [N_NODES * 64];   // relu(h3@lin2+b)

// Canonical int32 edge arrays + dtype-detection flag
__device__ int g_src[N_EDGES];
__device__ int g_dst[N_EDGES];
__device__ int g_flag[1];

// ---------------------------------------------------------------------------
// Edge-index preparation (int32 vs int64 JAX ambiguity) — unchanged, verified.
// ---------------------------------------------------------------------------
__global__ void flag_reset_kernel() { g_flag[0] = 0; }

__global__ __launch_bounds__(256) void detect_kernel(const int* __restrict__ w)
{
    int i = blockIdx.x * blockDim.x + threadIdx.x;
    long long idx = 2LL * i + 1;
    if (idx < 2LL * N_EDGES) {
        if (w[idx] != 0) atomicOr(&g_flag[0], 1);
    }
}

__global__ __launch_bounds__(256) void convert_kernel(const int* __restrict__ w)
{
    int e = blockIdx.x * blockDim.x + threadIdx.x;
    if (e >= N_EDGES) return;
    if (g_flag[0]) {
        g_src[e] = w[e];
        g_dst[e] = w[N_EDGES + e];
    } else {
        g_src[e] = w[2LL * e];
        g_dst[e] = w[2LL * (N_EDGES + e)];
    }
}

// ---------------------------------------------------------------------------
// tf32 helpers
// ---------------------------------------------------------------------------
__device__ __forceinline__ uint32_t f2tf32(float f) {
    uint32_t r;
    asm("cvt.rna.tf32.f32 %0, %1;" : "=r"(r) : "f"(f));
    return r;
}

__device__ __forceinline__ void mma_tf32(
    float& d0, float& d1, float& d2, float& d3,
    uint32_t a0, uint32_t a1, uint32_t a2, uint32_t a3,
    uint32_t b0, uint32_t b1)
{
    asm volatile(
        "mma.sync.aligned.m16n8k8.row.col.f32.tf32.tf32.f32 "
        "{%0,%1,%2,%3}, {%4,%5,%6,%7}, {%8,%9}, {%0,%1,%2,%3};"
        : "+f"(d0), "+f"(d1), "+f"(d2), "+f"(d3)
        : "r"(a0), "r"(a1), "r"(a2), "r"(a3), "r"(b0), "r"(b1));
}

// ---------------------------------------------------------------------------
// Dual-output GraphConv GEMM on tensor cores (tf32 mma.sync, 3xTF32 split).
//   C_rel  = A' @ W_rel            (no bias)
//   C_root = A' @ W_root + b       (bias)
// A' = reluA? relu(A) : A. grid.x = 2*(N/64): lower half rel, upper half root.
// Block: 256 threads = 8 warps (4 m-warps x 2 n-warps), BM=128, BN=64, BK=32.
// Warp tile 32x64... -> warp computes 32(m) x 32(n): 2 m-atoms x 4 n-atoms of
// m16n8k8. W is hi/lo-split once into smem; A split per-fragment in regs.
// Precision: D += Ah*Bh + Al*Bh + Ah*Bl  (error ~1e-6, fp32-class).
// ---------------------------------------------------------------------------
#define TBK 32
#define TAS_LD 132   // 128 + 4 pad -> LDS banks (k*4 + m) conflict-free
#define TWS_LD 68    // 64 + 4 pad  -> LDS banks (k*4 + n) conflict-free

__global__ __launch_bounds__(256) void gemm_dual_mma_kernel(
    const float* __restrict__ A,
    const float* __restrict__ W_rel,  float* __restrict__ C_rel,
    const float* __restrict__ W_root, const float* __restrict__ b_root,
    float* __restrict__ C_root,
    int M, int K, int N, int reluA)
{
    __shared__ float    As[TBK][TAS_LD];
    __shared__ uint32_t Wh[TBK][TWS_LD];
    __shared__ uint32_t Wl[TBK][TWS_LD];

    const int tid  = threadIdx.x;
    const int lane = tid & 31;
    const int wid  = tid >> 5;
    const int grp  = lane >> 2;   // 0..7
    const int tig  = lane & 3;    // 0..3
    const int m0   = (wid & 3) * 32;   // warp m offset in tile
    const int n0   = (wid >> 2) * 32;  // warp n offset in tile

    const int nt = N / 64;
    const int isRoot  = blockIdx.x >= nt;
    const int colTile = isRoot ? blockIdx.x - nt : blockIdx.x;
    const float* W    = isRoot ? W_root : W_rel;
    float* C          = isRoot ? C_root : C_rel;
    const float* bias = isRoot ? b_root : nullptr;

    // global-load assignments
    const int arow = blockIdx.y * 128 + (tid >> 1);  // one of 128 rows, 2 thr/row
    const int aks  = (tid & 1) * 16;                 // k sub-offset 0 or 16
    const int wkr  = tid >> 3;                       // 0..31 (k row of W tile)
    const int wnc  = (tid & 7) * 8;                  // 0..56 (n offset)
    const int wcol = colTile * 64 + wnc;

    float acc[2][4][4];
    #pragma unroll
    for (int i = 0; i < 2; i++)
        #pragma unroll
        for (int j = 0; j < 4; j++)
            #pragma unroll
            for (int q = 0; q < 4; q++) acc[i][j][q] = 0.f;

    for (int k0 = 0; k0 < K; k0 += TBK) {
        // ---- A tile: 128 rows x 32 k (raw fp32, relu fused) ----
        float4 av[4];
        if (arow < M) {
            const float* p = A + (size_t)arow * K + k0 + aks;
            av[0] = *reinterpret_cast<const float4*>(p + 0);
            av[1] = *reinterpret_cast<const float4*>(p + 4);
            av[2] = *reinterpret_cast<const float4*>(p + 8);
            av[3] = *reinterpret_cast<const float4*>(p + 12);
        } else {
            av[0] = av[1] = av[2] = av[3] = make_float4(0.f, 0.f, 0.f, 0.f);
        }
        if (reluA) {
            #pragma unroll
            for (int j = 0; j < 4; j++) {
                av[j].x = fmaxf(av[j].x, 0.f); av[j].y = fmaxf(av[j].y, 0.f);
                av[j].z = fmaxf(av[j].z, 0.f); av[j].w = fmaxf(av[j].w, 0.f);
            }
        }
        {
            const int r = tid >> 1;
            #pragma unroll
            for (int j = 0; j < 4; j++) {
                As[aks + 4*j + 0][r] = av[j].x;
                As[aks + 4*j + 1][r] = av[j].y;
                As[aks + 4*j + 2][r] = av[j].z;
                As[aks + 4*j + 3][r] = av[j].w;
            }
        }

        // ---- W tile: 32 k x 64 n, hi/lo split into smem ----
        {
            const float* p = W + (size_t)(k0 + wkr) * N + wcol;
            float4 w0 = *reinterpret_cast<const float4*>(p + 0);
            float4 w1 = *reinterpret_cast<const float4*>(p + 4);
            float wv[8] = {w0.x, w0.y, w0.z, w0.w, w1.x, w1.y, w1.z, w1.w};
            #pragma unroll
            for (int j = 0; j < 8; j++) {
                uint32_t hi = f2tf32(wv[j]);
                uint32_t lo = f2tf32(wv[j] - __uint_as_float(hi));
                Wh[wkr][wnc + j] = hi;
                Wl[wkr][wnc + j] = lo;
            }
        }

        __syncthreads();

        #pragma unroll
        for (int ka = 0; ka < 4; ka++) {
            const int kb = ka * 8;

            // B fragments (hi + lo) for 4 n-atoms
            uint32_t bh[4][2], bl[4][2];
            #pragma unroll
            for (int nat = 0; nat < 4; nat++) {
                const int nc = n0 + nat * 8 + grp;
                bh[nat][0] = Wh[kb + tig    ][nc];
                bh[nat][1] = Wh[kb + tig + 4][nc];
                bl[nat][0] = Wl[kb + tig    ][nc];
                bl[nat][1] = Wl[kb + tig + 4][nc];
            }

            #pragma unroll
            for (int mat = 0; mat < 2; mat++) {
                const int mb = m0 + mat * 16;
                const float ar0 = As[kb + tig    ][mb + grp    ];
                const float ar1 = As[kb + tig    ][mb + grp + 8];
                const float ar2 = As[kb + tig + 4][mb + grp    ];
                const float ar3 = As[kb + tig + 4][mb + grp + 8];
                const uint32_t ah0 = f2tf32(ar0), ah1 = f2tf32(ar1);
                const uint32_t ah2 = f2tf32(ar2), ah3 = f2tf32(ar3);
                const uint32_t al0 = f2tf32(ar0 - __uint_as_float(ah0));
                const uint32_t al1 = f2tf32(ar1 - __uint_as_float(ah1));
                const uint32_t al2 = f2tf32(ar2 - __uint_as_float(ah2));
                const uint32_t al3 = f2tf32(ar3 - __uint_as_float(ah3));

                #pragma unroll
                for (int nat = 0; nat < 4; nat++) {
                    float* d = acc[mat][nat];
                    mma_tf32(d[0], d[1], d[2], d[3], ah0, ah1, ah2, ah3, bh[nat][0], bh[nat][1]);
                    mma_tf32(d[0], d[1], d[2], d[3], al0, al1, al2, al3, bh[nat][0], bh[nat][1]);
                    mma_tf32(d[0], d[1], d[2], d[3], ah0, ah1, ah2, ah3, bl[nat][0], bl[nat][1]);
                }
            }
        }

        __syncthreads();
    }

    // ---- store (c layout: d0=(grp,2tig) d1=(grp,2tig+1) d2=(grp+8,..) d3) ----
    #pragma unroll
    for (int mat = 0; mat < 2; mat++) {
        const int rbase = blockIdx.y * 128 + m0 + mat * 16 + grp;
        #pragma unroll
        for (int half = 0; half < 2; half++) {
            const int r = rbase + half * 8;
            if (r >= M) continue;
            #pragma unroll
            for (int nat = 0; nat < 4; nat++) {
                const int c = colTile * 64 + n0 + nat * 8 + tig * 2;
                float v0 = acc[mat][nat][half * 2 + 0];
                float v1 = acc[mat][nat][half * 2 + 1];
                if (bias) { v0 += __ldg(bias + c); v1 += __ldg(bias + c + 1); }
                *reinterpret_cast<float2*>(C + (size_t)r * N + c) = make_float2(v0, v1);
            }
        }
    }
}

// ---------------------------------------------------------------------------
// FFMA GEMM (verified) — kept for the small MLP layers.
// BM=128, BN=64, BK=16, 128 threads, 8x8 microtile.
// ---------------------------------------------------------------------------
#define BM 128
#define BN 64
#define BK 16
#define AS_LD 132
#define WS_LD 68

__device__ __forceinline__ void gemm_tile8(
    const float* __restrict__ A, const float* __restrict__ W,
    int M, int K, int N, int reluA,
    int rowTile, int colTile, float acc[8][8],
    float (*As)[AS_LD], float (*Ws)[WS_LD])
{
    const int tid = threadIdx.x;
    const int tx = tid & 7;
    const int ty = tid >> 3;

    const int arow = rowTile * BM + tid;
    const int wk   = tid >> 3;
    const int wc   = (tid & 7) * 8;
    const int wcol = colTile * BN + wc;

    for (int k0 = 0; k0 < K; k0 += BK) {
        float4 a0 = make_float4(0.f,0.f,0.f,0.f), a1 = a0, a2 = a0, a3 = a0;
        if (arow < M) {
            const float* p = A + (size_t)arow * K + k0;
            a0 = *reinterpret_cast<const float4*>(p + 0);
            a1 = *reinterpret_cast<const float4*>(p + 4);
            a2 = *reinterpret_cast<const float4*>(p + 8);
            a3 = *reinterpret_cast<const float4*>(p + 12);
        }
        if (reluA) {
            a0.x=fmaxf(a0.x,0.f); a0.y=fmaxf(a0.y,0.f); a0.z=fmaxf(a0.z,0.f); a0.w=fmaxf(a0.w,0.f);
            a1.x=fmaxf(a1.x,0.f); a1.y=fmaxf(a1.y,0.f); a1.z=fmaxf(a1.z,0.f); a1.w=fmaxf(a1.w,0.f);
            a2.x=fmaxf(a2.x,0.f); a2.y=fmaxf(a2.y,0.f); a2.z=fmaxf(a2.z,0.f); a2.w=fmaxf(a2.w,0.f);
            a3.x=fmaxf(a3.x,0.f); a3.y=fmaxf(a3.y,0.f); a3.z=fmaxf(a3.z,0.f); a3.w=fmaxf(a3.w,0.f);
        }
        As[ 0][tid]=a0.x; As[ 1][tid]=a0.y; As[ 2][tid]=a0.z; As[ 3][tid]=a0.w;
        As[ 4][tid]=a1.x; As[ 5][tid]=a1.y; As[ 6][tid]=a1.z; As[ 7][tid]=a1.w;
        As[ 8][tid]=a2.x; As[ 9][tid]=a2.y; As[10][tid]=a2.z; As[11][tid]=a2.w;
        As[12][tid]=a3.x; As[13][tid]=a3.y; As[14][tid]=a3.z; As[15][tid]=a3.w;

        {
            const float* p = W + (size_t)(k0 + wk) * N + wcol;
            float4 w0 = *reinterpret_cast<const float4*>(p + 0);
            float4 w1 = *reinterpret_cast<const float4*>(p + 4);
            *reinterpret_cast<float4*>(&Ws[wk][wc + 0]) = w0;
            *reinterpret_cast<float4*>(&Ws[wk][wc + 4]) = w1;
        }

        __syncthreads();

        #pragma unroll
        for (int kk = 0; kk < BK; kk++) {
            float4 va0 = *reinterpret_cast<const float4*>(&As[kk][ty * 8 + 0]);
            float4 va1 = *reinterpret_cast<const float4*>(&As[kk][ty * 8 + 4]);
            float4 vw0 = *reinterpret_cast<const float4*>(&Ws[kk][tx * 8 + 0]);
            float4 vw1 = *reinterpret_cast<const float4*>(&Ws[kk][tx * 8 + 4]);
            float a[8] = {va0.x, va0.y, va0.z, va0.w, va1.x, va1.y, va1.z, va1.w};
            float w[8] = {vw0.x, vw0.y, vw0.z, vw0.w, vw1.x, vw1.y, vw1.z, vw1.w};
            #pragma unroll
            for (int i = 0; i < 8; i++)
                #pragma unroll
                for (int j = 0; j < 8; j++)
                    acc[i][j] = fmaf(a[i], w[j], acc[i][j]);
        }

        __syncthreads();
    }
}

__device__ __forceinline__ void gemm_store8(
    const float* __restrict__ bias, float* __restrict__ C,
    int M, int N, int reluC, int rowTile, int colTile, float acc[8][8])
{
    const int tid = threadIdx.x;
    const int tx = tid & 7;
    const int ty = tid >> 3;
    const int row0 = rowTile * BM + ty * 8;
    const int col0 = colTile * BN + tx * 8;

    float bv[8];
    #pragma unroll
    for (int j = 0; j < 8; j++) bv[j] = bias ? __ldg(bias + col0 + j) : 0.f;

    #pragma unroll
    for (int i = 0; i < 8; i++) {
        int r = row0 + i;
        if (r >= M) break;
        float o[8];
        #pragma unroll
        for (int j = 0; j < 8; j++) {
            o[j] = acc[i][j] + bv[j];
            if (reluC) o[j] = fmaxf(o[j], 0.f);
        }
        float* p = C + (size_t)r * N + col0;
        *reinterpret_cast<float4*>(p + 0) = make_float4(o[0], o[1], o[2], o[3]);
        *reinterpret_cast<float4*>(p + 4) = make_float4(o[4], o[5], o[6], o[7]);
    }
}

__global__ __launch_bounds__(128) void gemm_kernel(
    const float* __restrict__ A, const float* __restrict__ W,
    const float* __restrict__ bias, float* __restrict__ C,
    int M, int K, int N, int reluA, int reluC)
{
    __shared__ float As[BK][AS_LD];
    __shared__ float Ws[BK][WS_LD];
    float acc[8][8] = {};
    gemm_tile8(A, W, M, K, N, reluA, blockIdx.y, blockIdx.x, acc, As, Ws);
    gemm_store8(bias, C, M, N, reluC, blockIdx.y, blockIdx.x, acc);
}

// ---------------------------------------------------------------------------
// Edge scatter-add (red.global.add.v4.f32) — unchanged, verified.
// ---------------------------------------------------------------------------
template <int DIM>
__global__ __launch_bounds__(256) void scatter_kernel(
    const float* __restrict__ feat,
    float* __restrict__ out,
    int n_edges)
{
    constexpr int CH  = DIM / 4;
    constexpr int EPW = 32 / CH;
    const int warp = (blockIdx.x * blockDim.x + threadIdx.x) >> 5;
    const int lane = threadIdx.x & 31;
    const int sub  = lane / CH;
    const int cc   = lane % CH;

    const int e = warp * EPW + sub;
    if (e >= n_edges) return;

    const int s = g_src[e];
    const int d = g_dst[e];

    const float4 v = *reinterpret_cast<const float4*>(feat + (size_t)s * DIM + cc * 4);
    float* p = out + (size_t)d * DIM + cc * 4;
    asm volatile("red.global.add.v4.f32 [%0], {%1, %2, %3, %4};"
                 :: "l"(p), "f"(v.x), "f"(v.y), "f"(v.z), "f"(v.w)
                 : "memory");
}

// ---------------------------------------------------------------------------
// Head: log_softmax(h4 @ lin3_w + lin3_b) — unchanged, verified.
// ---------------------------------------------------------------------------
__global__ __launch_bounds__(256) void head_kernel(
    const float* __restrict__ h4,
    const float* __restrict__ W,
    const float* __restrict__ b,
    float* __restrict__ out,
    int M)
{
    const int warp = (blockIdx.x * blockDim.x + threadIdx.x) >> 5;
    const int lane = threadIdx.x & 31;
    if (warp >= M) return;

    const float a0 = h4[(size_t)warp * 64 + lane];
    const float a1 = h4[(size_t)warp * 64 + 32 + lane];

    float acc[10];
    #pragma unroll
    for (int c = 0; c < 10; c++)
        acc[c] = fmaf(a0, __ldg(W + lane * 10 + c),
                      a1 * __ldg(W + (32 + lane) * 10 + c));

    #pragma unroll
    for (int off = 16; off > 0; off >>= 1)
        #pragma unroll
        for (int c = 0; c < 10; c++)
            acc[c] += __shfl_down_sync(0xffffffffu, acc[c], off);

    if (lane == 0) {
        float m = -1e30f;
        #pragma unroll
        for (int c = 0; c < 10; c++) {
            acc[c] += __ldg(b + c);
            m = fmaxf(m, acc[c]);
        }
        float s = 0.f;
        #pragma unroll
        for (int c = 0; c < 10; c++) s += expf(acc[c] - m);
        const float lse = m + logf(s);
        #pragma unroll
        for (int c = 0; c < 10; c++)
            out[(size_t)warp * 10 + c] = acc[c] - lse;
    }
}

// ---------------------------------------------------------------------------
extern "C" void kernel_launch(void* const* d_in, const int* in_sizes, int n_in,
                              void* d_out, int out_size)
{
    const float* x       = (const float*)d_in[0];
    const int*   ei_raw  = (const int*)  d_in[1];
    const float* W1_rel  = (const float*)d_in[2];
    const float* W1_root = (const float*)d_in[3];
    const float* b1      = (const float*)d_in[4];
    const float* W2_rel  = (const float*)d_in[5];
    const float* W2_root = (const float*)d_in[6];
    const float* b2      = (const float*)d_in[7];
    const float* lin1_w  = (const float*)d_in[8];
    const float* lin1_b  = (const float*)d_in[9];
    const float* lin2_w  = (const float*)d_in[10];
    const float* lin2_b  = (const float*)d_in[11];
    const float* lin3_w  = (const float*)d_in[12];
    const float* lin3_b  = (const float*)d_in[13];
    float* out = (float*)d_out;

    float *xr1, *h1, *xr2, *h2, *h3, *h4;
    cudaGetSymbolAddress((void**)&xr1, g_xr1);
    cudaGetSymbolAddress((void**)&h1,  g_h1);
    cudaGetSymbolAddress((void**)&xr2, g_xr2);
    cudaGetSymbolAddress((void**)&h2,  g_h2);
    cudaGetSymbolAddress((void**)&h3,  g_h3);
    cudaGetSymbolAddress((void**)&h4,  g_h4);

    // ---- Edge-index normalization (dtype auto-detect) ----
    flag_reset_kernel<<<1, 1>>>();
    detect_kernel<<<(N_EDGES + 255) / 256, 256>>>(ei_raw);
    convert_kernel<<<(N_EDGES + 255) / 256, 256>>>(ei_raw);

    const int mbr = (N_NODES + 127) / 128;   // 157

    // ---- GraphConv 1 (tensor cores): xr1 = x@W1_rel ; h1 = x@W1_root + b1 ----
    gemm_dual_mma_kernel<<<dim3(4, mbr), 256>>>(x, W1_rel, xr1, W1_root, b1, h1,
                                                N_NODES, 256, 128, 0);
    {
        int blocks = (N_EDGES + 7) / 8;
        scatter_kernel<128><<<blocks, 256>>>(xr1, h1, N_EDGES);
    }

    // ---- GraphConv 2 (tensor cores, relu fused into A-load) ----
    gemm_dual_mma_kernel<<<dim3(2, mbr), 256>>>(h1, W2_rel, xr2, W2_root, b2, h2,
                                                N_NODES, 128, 64, 1);
    {
        int blocks = (N_EDGES + 15) / 16;
        scatter_kernel<64><<<blocks, 256>>>(xr2, h2, N_EDGES);
    }

    // ---- MLP head (verified FFMA path) ----
    gemm_kernel<<<dim3(2, mbr), 128>>>(h2, lin1_w, lin1_b, h3, N_NODES, 64, 128, 0, 1);
    gemm_kernel<<<dim3(1, mbr), 128>>>(h3, lin2_w, lin2_b, h4, N_NODES, 128, 64, 0, 1);

    {
        int blocks = (N_NODES * 32 + 255) / 256;
        head_kernel<<<blocks, 256>>>(h4, lin3_w, lin3_b, out, N_NODES);
    }
}

// round 11
// speedup vs baseline: 1.2637x; 1.1512x over previous
#include <cuda_runtime.h>
#include <cuda_bf16.h>
#include <cstdint>

#define N_NODES 20000
#define N_EDGES 320000

// Scratch (static __device__ arrays — no allocation allowed). 16B-aligned.
__device__ __align__(16) float g_xr1[N_NODES * 128];  // x @ W1_rel
__device__ __align__(16) float g_h1 [N_NODES * 128];  // conv1 output (pre-relu)
__device__ __align__(16) float g_xr2[N_NODES * 64];   // relu(h1) @ W2_rel
__device__ __align__(16) float g_h2 [N_NODES * 64];   // conv2 output
__device__ __align__(16) float g_h3 [N_NODES * 128];  // relu(h2@lin1+b)
__device__ __align__(16) float g_h4 [N_NODES * 64];   // relu(h3@lin2+b)

// Canonical int32 edge arrays + dtype-detection flag
__device__ int g_src[N_EDGES];
__device__ int g_dst[N_EDGES];
__device__ int g_flag[1];

// ---------------------------------------------------------------------------
// Edge-index preparation (int32 vs int64 JAX ambiguity) — unchanged, verified.
// ---------------------------------------------------------------------------
__global__ void flag_reset_kernel() { g_flag[0] = 0; }

__global__ __launch_bounds__(256) void detect_kernel(const int* __restrict__ w)
{
    int i = blockIdx.x * blockDim.x + threadIdx.x;
    long long idx = 2LL * i + 1;
    if (idx < 2LL * N_EDGES) {
        if (w[idx] != 0) atomicOr(&g_flag[0], 1);
    }
}

__global__ __launch_bounds__(256) void convert_kernel(const int* __restrict__ w)
{
    int e = blockIdx.x * blockDim.x + threadIdx.x;
    if (e >= N_EDGES) return;
    if (g_flag[0]) {
        g_src[e] = w[e];
        g_dst[e] = w[N_EDGES + e];
    } else {
        g_src[e] = w[2LL * e];
        g_dst[e] = w[2LL * (N_EDGES + e)];
    }
}

// ---------------------------------------------------------------------------
// tf32 helpers
// ---------------------------------------------------------------------------
__device__ __forceinline__ uint32_t f2tf32(float f) {
    uint32_t r;
    asm("cvt.rna.tf32.f32 %0, %1;" : "=r"(r) : "f"(f));
    return r;
}

__device__ __forceinline__ void mma_tf32(
    float& d0, float& d1, float& d2, float& d3,
    uint32_t a0, uint32_t a1, uint32_t a2, uint32_t a3,
    uint32_t b0, uint32_t b1)
{
    asm volatile(
        "mma.sync.aligned.m16n8k8.row.col.f32.tf32.tf32.f32 "
        "{%0,%1,%2,%3}, {%4,%5,%6,%7}, {%8,%9}, {%0,%1,%2,%3};"
        : "+f"(d0), "+f"(d1), "+f"(d2), "+f"(d3)
        : "r"(a0), "r"(a1), "r"(a2), "r"(a3), "r"(b0), "r"(b1));
}

// ---------------------------------------------------------------------------
// Tensor-core GEMM core (tf32 mma.sync, 3xTF32 split, cp.async double-buffer)
// BM=128, BN=64, BK=32; 256 threads = 8 warps (4 m-warps x 2 n-warps).
// Warp computes 32(m) x 32(n): 2 m-atoms x 4 n-atoms of m16n8k8.
// A stored [m][k] raw fp32 (cp.async can't transpose), LD=36: fragment access
// addr = 36*(mb+grp) + kb+tig -> banks (4*grp + tig) mod 32 all distinct.
// W stored [k][n] raw fp32, LD=68: addr = 68*(kb+tig) + nc -> (4*tig + grp+..)
// conflict-free. hi/lo tf32 split done at fragment load (ALU cheap, LDS dear).
// Precision: D += Ah*Bh + Al*Bh + Ah*Bl (verified: rel_err ~2.6e-6).
// ---------------------------------------------------------------------------
#define TBK 32
#define ALD 36
#define WLD 68

struct alignas(16) MmaSmem {
    float As[2][128][ALD];   // 36,864 B
    float Ws[2][TBK][WLD];   // 17,408 B
};
static const int MMA_SMEM_BYTES = (int)sizeof(MmaSmem);  // 54,272 B

__device__ __forceinline__ void mma_issue_tile(
    MmaSmem& sm, int buf,
    const float* __restrict__ A, const float* __restrict__ W,
    int M, int K, int N, int rowBase, int wcolBase, int k0, int tid)
{
    float (*As)[ALD] = sm.As[buf];
    float (*Ws)[WLD] = sm.Ws[buf];
    // A: 128 rows x 32 k. Two threads per row, 16 floats each (4 x 16B).
    {
        const int cr  = tid >> 1;
        const int ckh = (tid & 1) * 16;
        const int arow = rowBase + cr;
        const float* src = A + (size_t)arow * K + k0 + ckh;
        uint32_t dst = (uint32_t)__cvta_generic_to_shared(&As[cr][ckh]);
        const int ok = (arow < M) ? 16 : 0;   // zero-fill OOB rows
        #pragma unroll
        for (int j = 0; j < 4; j++)
            asm volatile("cp.async.cg.shared.global [%0], [%1], 16, %2;"
                         :: "r"(dst + 16u * j), "l"(src + 4 * j), "r"(ok)
                         : "memory");
    }
    // W: 32 k x 64 n. One thread per (k, 8n), 2 x 16B.
    {
        const int cwk = tid >> 3;
        const int cwn = (tid & 7) * 8;
        const float* src = W + (size_t)(k0 + cwk) * N + wcolBase + cwn;
        uint32_t dst = (uint32_t)__cvta_generic_to_shared(&Ws[cwk][cwn]);
        asm volatile("cp.async.cg.shared.global [%0], [%1], 16;"
                     :: "r"(dst), "l"(src) : "memory");
        asm volatile("cp.async.cg.shared.global [%0], [%1], 16;"
                     :: "r"(dst + 16u), "l"(src + 4) : "memory");
    }
    asm volatile("cp.async.commit_group;" ::: "memory");
}

__device__ __forceinline__ void mma_core(
    const float* __restrict__ A, const float* __restrict__ W,
    const float* __restrict__ bias, float* __restrict__ C,
    int M, int K, int N, int reluA, int reluC, int colTile)
{
    extern __shared__ char smem_raw[];
    MmaSmem& sm = *reinterpret_cast<MmaSmem*>(smem_raw);

    const int tid  = threadIdx.x;
    const int lane = tid & 31;
    const int wid  = tid >> 5;
    const int grp  = lane >> 2;        // 0..7
    const int tig  = lane & 3;         // 0..3
    const int m0   = (wid & 3) * 32;
    const int n0   = (wid >> 2) * 32;
    const int rowBase  = blockIdx.y * 128;
    const int wcolBase = colTile * 64;

    float acc[2][4][4] = {};

    const int ntk = K / TBK;
    mma_issue_tile(sm, 0, A, W, M, K, N, rowBase, wcolBase, 0, tid);

    for (int t = 0; t < ntk; t++) {
        if (t + 1 < ntk) {
            mma_issue_tile(sm, (t + 1) & 1, A, W, M, K, N, rowBase, wcolBase,
                           (t + 1) * TBK, tid);
            asm volatile("cp.async.wait_group 1;" ::: "memory");
        } else {
            asm volatile("cp.async.wait_group 0;" ::: "memory");
        }
        __syncthreads();

        float (*As)[ALD] = sm.As[t & 1];
        float (*Ws)[WLD] = sm.Ws[t & 1];

        #pragma unroll
        for (int ka = 0; ka < 4; ka++) {
            const int kb = ka * 8;

            // B fragments: load raw, split hi/lo here (2 LDS instead of 4)
            uint32_t bh[4][2], bl[4][2];
            #pragma unroll
            for (int nat = 0; nat < 4; nat++) {
                const int nc = n0 + nat * 8 + grp;
                const float w0 = Ws[kb + tig    ][nc];
                const float w1 = Ws[kb + tig + 4][nc];
                bh[nat][0] = f2tf32(w0);
                bh[nat][1] = f2tf32(w1);
                bl[nat][0] = f2tf32(w0 - __uint_as_float(bh[nat][0]));
                bl[nat][1] = f2tf32(w1 - __uint_as_float(bh[nat][1]));
            }

            #pragma unroll
            for (int mat = 0; mat < 2; mat++) {
                const int mb = m0 + mat * 16;
                float ar0 = As[mb + grp    ][kb + tig    ];
                float ar1 = As[mb + grp + 8][kb + tig    ];
                float ar2 = As[mb + grp    ][kb + tig + 4];
                float ar3 = As[mb + grp + 8][kb + tig + 4];
                if (reluA) {
                    ar0 = fmaxf(ar0, 0.f); ar1 = fmaxf(ar1, 0.f);
                    ar2 = fmaxf(ar2, 0.f); ar3 = fmaxf(ar3, 0.f);
                }
                const uint32_t ah0 = f2tf32(ar0), ah1 = f2tf32(ar1);
                const uint32_t ah2 = f2tf32(ar2), ah3 = f2tf32(ar3);
                const uint32_t al0 = f2tf32(ar0 - __uint_as_float(ah0));
                const uint32_t al1 = f2tf32(ar1 - __uint_as_float(ah1));
                const uint32_t al2 = f2tf32(ar2 - __uint_as_float(ah2));
                const uint32_t al3 = f2tf32(ar3 - __uint_as_float(ah3));

                #pragma unroll
                for (int nat = 0; nat < 4; nat++) {
                    float* d = acc[mat][nat];
                    mma_tf32(d[0], d[1], d[2], d[3], ah0, ah1, ah2, ah3, bh[nat][0], bh[nat][1]);
                    mma_tf32(d[0], d[1], d[2], d[3], al0, al1, al2, al3, bh[nat][0], bh[nat][1]);
                    mma_tf32(d[0], d[1], d[2], d[3], ah0, ah1, ah2, ah3, bl[nat][0], bl[nat][1]);
                }
            }
        }
        __syncthreads();
    }

    // store (c frag: d0=(grp,2tig) d1=(grp,2tig+1) d2=(grp+8,2tig) d3=..+1)
    #pragma unroll
    for (int mat = 0; mat < 2; mat++) {
        const int rb = rowBase + m0 + mat * 16 + grp;
        #pragma unroll
        for (int half = 0; half < 2; half++) {
            const int r = rb + half * 8;
            if (r >= M) continue;
            #pragma unroll
            for (int nat = 0; nat < 4; nat++) {
                const int c = wcolBase + n0 + nat * 8 + tig * 2;
                float v0 = acc[mat][nat][half * 2 + 0];
                float v1 = acc[mat][nat][half * 2 + 1];
                if (bias) { v0 += __ldg(bias + c); v1 += __ldg(bias + c + 1); }
                if (reluC) { v0 = fmaxf(v0, 0.f); v1 = fmaxf(v1, 0.f); }
                *reinterpret_cast<float2*>(C + (size_t)r * N + c) = make_float2(v0, v1);
            }
        }
    }
}

// Dual-output GraphConv GEMM: grid.x = 2*(N/64); lower half rel, upper root.
__global__ __launch_bounds__(256) void gemm_dual_mma_kernel(
    const float* __restrict__ A,
    const float* __restrict__ W_rel,  float* __restrict__ C_rel,
    const float* __restrict__ W_root, const float* __restrict__ b_root,
    float* __restrict__ C_root,
    int M, int K, int N, int reluA)
{
    const int nt = N / 64;
    const int isRoot  = blockIdx.x >= nt;
    const int colTile = isRoot ? blockIdx.x - nt : blockIdx.x;
    mma_core(A,
             isRoot ? W_root : W_rel,
             isRoot ? b_root : nullptr,
             isRoot ? C_root : C_rel,
             M, K, N, reluA, /*reluC=*/0, colTile);
}

// Single-output GEMM (MLP layers): C = act(A@W + bias)
__global__ __launch_bounds__(256) void gemm_mma_kernel(
    const float* __restrict__ A, const float* __restrict__ W,
    const float* __restrict__ bias, float* __restrict__ C,
    int M, int K, int N, int reluA, int reluC)
{
    mma_core(A, W, bias, C, M, K, N, reluA, reluC, blockIdx.x);
}

// ---------------------------------------------------------------------------
// Edge scatter-add (red.global.add.v4.f32) — unchanged, verified.
// ---------------------------------------------------------------------------
template <int DIM>
__global__ __launch_bounds__(256) void scatter_kernel(
    const float* __restrict__ feat,
    float* __restrict__ out,
    int n_edges)
{
    constexpr int CH  = DIM / 4;
    constexpr int EPW = 32 / CH;
    const int warp = (blockIdx.x * blockDim.x + threadIdx.x) >> 5;
    const int lane = threadIdx.x & 31;
    const int sub  = lane / CH;
    const int cc   = lane % CH;

    const int e = warp * EPW + sub;
    if (e >= n_edges) return;

    const int s = g_src[e];
    const int d = g_dst[e];

    const float4 v = *reinterpret_cast<const float4*>(feat + (size_t)s * DIM + cc * 4);
    float* p = out + (size_t)d * DIM + cc * 4;
    asm volatile("red.global.add.v4.f32 [%0], {%1, %2, %3, %4};"
                 :: "l"(p), "f"(v.x), "f"(v.y), "f"(v.z), "f"(v.w)
                 : "memory");
}

// ---------------------------------------------------------------------------
// Head: log_softmax(h4 @ lin3_w + lin3_b) — unchanged, verified.
// ---------------------------------------------------------------------------
__global__ __launch_bounds__(256) void head_kernel(
    const float* __restrict__ h4,
    const float* __restrict__ W,
    const float* __restrict__ b,
    float* __restrict__ out,
    int M)
{
    const int warp = (blockIdx.x * blockDim.x + threadIdx.x) >> 5;
    const int lane = threadIdx.x & 31;
    if (warp >= M) return;

    const float a0 = h4[(size_t)warp * 64 + lane];
    const float a1 = h4[(size_t)warp * 64 + 32 + lane];

    float acc[10];
    #pragma unroll
    for (int c = 0; c < 10; c++)
        acc[c] = fmaf(a0, __ldg(W + lane * 10 + c),
                      a1 * __ldg(W + (32 + lane) * 10 + c));

    #pragma unroll
    for (int off = 16; off > 0; off >>= 1)
        #pragma unroll
        for (int c = 0; c < 10; c++)
            acc[c] += __shfl_down_sync(0xffffffffu, acc[c], off);

    if (lane == 0) {
        float m = -1e30f;
        #pragma unroll
        for (int c = 0; c < 10; c++) {
            acc[c] += __ldg(b + c);
            m = fmaxf(m, acc[c]);
        }
        float s = 0.f;
        #pragma unroll
        for (int c = 0; c < 10; c++) s += expf(acc[c] - m);
        const float lse = m + logf(s);
        #pragma unroll
        for (int c = 0; c < 10; c++)
            out[(size_t)warp * 10 + c] = acc[c] - lse;
    }
}

// ---------------------------------------------------------------------------
extern "C" void kernel_launch(void* const* d_in, const int* in_sizes, int n_in,
                              void* d_out, int out_size)
{
    const float* x       = (const float*)d_in[0];
    const int*   ei_raw  = (const int*)  d_in[1];
    const float* W1_rel  = (const float*)d_in[2];
    const float* W1_root = (const float*)d_in[3];
    const float* b1      = (const float*)d_in[4];
    const float* W2_rel  = (const float*)d_in[5];
    const float* W2_root = (const float*)d_in[6];
    const float* b2      = (const float*)d_in[7];
    const float* lin1_w  = (const float*)d_in[8];
    const float* lin1_b  = (const float*)d_in[9];
    const float* lin2_w  = (const float*)d_in[10];
    const float* lin2_b  = (const float*)d_in[11];
    const float* lin3_w  = (const float*)d_in[12];
    const float* lin3_b  = (const float*)d_in[13];
    float* out = (float*)d_out;

    float *xr1, *h1, *xr2, *h2, *h3, *h4;
    cudaGetSymbolAddress((void**)&xr1, g_xr1);
    cudaGetSymbolAddress((void**)&h1,  g_h1);
    cudaGetSymbolAddress((void**)&xr2, g_xr2);
    cudaGetSymbolAddress((void**)&h2,  g_h2);
    cudaGetSymbolAddress((void**)&h3,  g_h3);
    cudaGetSymbolAddress((void**)&h4,  g_h4);

    // Allow >48KB dynamic smem for the mma kernels (idempotent host calls).
    cudaFuncSetAttribute(gemm_dual_mma_kernel,
                         cudaFuncAttributeMaxDynamicSharedMemorySize, MMA_SMEM_BYTES);
    cudaFuncSetAttribute(gemm_mma_kernel,
                         cudaFuncAttributeMaxDynamicSharedMemorySize, MMA_SMEM_BYTES);

    // ---- Edge-index normalization (dtype auto-detect) ----
    flag_reset_kernel<<<1, 1>>>();
    detect_kernel<<<(N_EDGES + 255) / 256, 256>>>(ei_raw);
    convert_kernel<<<(N_EDGES + 255) / 256, 256>>>(ei_raw);

    const int mbr = (N_NODES + 127) / 128;   // 157

    // ---- GraphConv 1 (tensor cores): xr1 = x@W1_rel ; h1 = x@W1_root + b1 ----
    gemm_dual_mma_kernel<<<dim3(4, mbr), 256, MMA_SMEM_BYTES>>>(
        x, W1_rel, xr1, W1_root, b1, h1, N_NODES, 256, 128, 0);
    {
        int blocks = (N_EDGES + 7) / 8;
        scatter_kernel<128><<<blocks, 256>>>(xr1, h1, N_EDGES);
    }

    // ---- GraphConv 2 (tensor cores, relu fused into A fragments) ----
    gemm_dual_mma_kernel<<<dim3(2, mbr), 256, MMA_SMEM_BYTES>>>(
        h1, W2_rel, xr2, W2_root, b2, h2, N_NODES, 128, 64, 1);
    {
        int blocks = (N_EDGES + 15) / 16;
        scatter_kernel<64><<<blocks, 256>>>(xr2, h2, N_EDGES);
    }

    // ---- MLP head (tensor cores, fused bias+relu) ----
    gemm_mma_kernel<<<dim3(2, mbr), 256, MMA_SMEM_BYTES>>>(
        h2, lin1_w, lin1_b, h3, N_NODES, 64, 128, 0, 1);
    gemm_mma_kernel<<<dim3(1, mbr), 256, MMA_SMEM_BYTES>>>(
        h3, lin2_w, lin2_b, h4, N_NODES, 128, 64, 0, 1);

    {
        int blocks = (N_NODES * 32 + 255) / 256;
        head_kernel<<<blocks, 256>>>(h4, lin3_w, lin3_b, out, N_NODES);
    }
}